// round 15
// baseline (speedup 1.0000x reference)
#include <cuda_runtime.h>
#include <math.h>

#define BDIM   256
#define STAGES 2          // full-row stages per CTA
#define CTAS   3          // persistent CTAs per SM (3 barrier domains)
#define MAXG   4096

// Scratch (allocation-free): per-CTA partial {loss_sum, keep_count} + queues.
__device__ float2       g_part[MAXG];
__device__ unsigned int g_done = 0;
__device__ unsigned int g_next = 0;    // dynamic row queue head

__device__ __forceinline__ float warp_sum(float v) {
#pragma unroll
    for (int o = 16; o > 0; o >>= 1)
        v += __shfl_xor_sync(0xffffffffu, v, o);
    return v;
}

__device__ __forceinline__ unsigned int smem_u32(const void* p) {
    return (unsigned int)__cvta_generic_to_shared(p);
}
__device__ __forceinline__ void mbar_init(unsigned int mb, unsigned int cnt) {
    asm volatile("mbarrier.init.shared.b64 [%0], %1;" :: "r"(mb), "r"(cnt) : "memory");
}
__device__ __forceinline__ void mbar_expect_tx(unsigned int mb, unsigned int bytes) {
    asm volatile("mbarrier.arrive.expect_tx.shared.b64 _, [%0], %1;"
                 :: "r"(mb), "r"(bytes) : "memory");
}
__device__ __forceinline__ void bulk_g2s(unsigned int dst, const void* src,
                                         unsigned int bytes, unsigned int mb) {
    asm volatile(
        "cp.async.bulk.shared::cta.global.mbarrier::complete_tx::bytes [%0], [%1], %2, [%3];"
        :: "r"(dst), "l"(src), "r"(bytes), "r"(mb) : "memory");
}
__device__ __forceinline__ void mbar_wait(unsigned int mb, unsigned int parity) {
    asm volatile(
        "{\n\t"
        ".reg .pred P;\n\t"
        "WAIT_%=:\n\t"
        "mbarrier.try_wait.parity.acquire.cta.shared::cta.b64 P, [%0], %1, 0x989680;\n\t"
        "@P bra.uni DONE_%=;\n\t"
        "bra.uni WAIT_%=;\n\t"
        "DONE_%=:\n\t"
        "}"
        :: "r"(mb), "r"(parity) : "memory");
}

// Persistent CTA (CTAS/SM), STAGES x 32KB cp.async.bulk pipeline through smem,
// dynamic row queue (atomicAdd) for perfect load balance across SM speed spread.
// Measured at the B300 LTS chip cap (~6.4 TB/s).
template <int NL>
__global__ void __launch_bounds__(BDIM, CTAS)
pers_kernel(const float* __restrict__ prd, const int* __restrict__ tgt,
            float* __restrict__ out, int xc, int B, int G)
{
    constexpr int ROW_BYTES = NL * 4;          // 32768
    constexpr int ROW_F4    = NL / 4;          // 2048 float4

    extern __shared__ float4 stage[];          // STAGES * ROW_F4

    __shared__ __align__(8) unsigned long long mbar_store[STAGES];
    __shared__ int   s_rowid[STAGES];          // row id held in each stage slot
    __shared__ float sh[2][2][BDIM / 32];      // [iter parity][{z,sel}][warp]
    __shared__ int   shn[2][BDIM / 32];        // [iter parity][warp] hit counts
    __shared__ int   s_nl[2];
    __shared__ int   s_last;

    const int tid = threadIdx.x;
    const int w   = tid >> 5;
    const int l   = tid & 31;
    const int X   = xc - 1;
    const int bid = blockIdx.x;

    unsigned int mb[STAGES];
#pragma unroll
    for (int s = 0; s < STAGES; s++) mb[s] = smem_u32(&mbar_store[s]);

    if (tid == 0) {
#pragma unroll
        for (int s = 0; s < STAGES; s++) mbar_init(mb[s], 1);
        // one atomic grabs the initial STAGES rows (less launch-burst contention)
        unsigned int base = atomicAdd(&g_next, (unsigned int)STAGES);
#pragma unroll
        for (int j = 0; j < STAGES; j++) {
            unsigned int r = base + j;
            s_rowid[j] = (r < (unsigned int)B) ? (int)r : -1;
            if (r < (unsigned int)B) {
                mbar_expect_tx(mb[j], ROW_BYTES);
                bulk_g2s(smem_u32(stage + j * ROW_F4),
                         prd + (size_t)r * NL, ROW_BYTES, mb[j]);
            }
        }
    }
    __syncthreads();

    float acc_loss = 0.0f;   // meaningful in thread 0 only
    float acc_keep = 0.0f;

    int s = 0, ph = 0, wraps = 0;
    for (int k = 0; ; k++) {
        // row id for this slot: written by tid0 >=1 sync ago -> safe
        const int row = s_rowid[s];
        if (row < 0) break;
        const int par = k & 1;

        // labels for THIS row: issue LDG now, consumed mid-compute (hidden)
        int labv = 0;
        if (tid <= X) labv = __ldg(tgt + (size_t)row * xc + tid);

        mbar_wait(mb[s], ph);

        const float4* rowp = stage + s * ROW_F4;
        const float*  rowf = (const float*)rowp;

        // exp-sum of the whole row from smem
        float lsum = 0.0f;
#pragma unroll
        for (int j = 0; j < 8; j++) {
            float4 v = rowp[tid + j * BDIM];
            lsum += __expf(v.x); lsum += __expf(v.y);
            lsum += __expf(v.z); lsum += __expf(v.w);
        }

        // label gather straight from smem (row is resident)
        bool  hit = (tid < X) && (labv != 0);
        float sel = hit ? __expf(rowf[labv]) : 0.0f;
        if (tid == X) s_nl[par] = labv;        // num_listed

        // per-row block reduction: 2 float warp-sums + ballot popc
        float r0 = warp_sum(lsum);
        float r1 = warp_sum(sel);
        unsigned int bal = __ballot_sync(0xffffffffu, hit);
        if (l == 0) {
            sh[par][0][w] = r0;
            sh[par][1][w] = r1;
            shn[par][w]   = __popc(bal);
        }
        __syncthreads();   // all reads of stage s complete past this point

        // refill stage s with the next queued row
        if (tid == 0) {
            unsigned int nr = atomicAdd(&g_next, 1u);
            s_rowid[s] = (nr < (unsigned int)B) ? (int)nr : -1;
            if (nr < (unsigned int)B) {
                mbar_expect_tx(mb[s], ROW_BYTES);
                bulk_g2s(smem_u32(stage + s * ROW_F4),
                         prd + (size_t)nr * NL, ROW_BYTES, mb[s]);
            }
        }

        if (tid < 32) {
            const int NW = BDIM / 32;
            float z  = (tid < NW) ? sh[par][0][tid] : 0.0f;
            float y  = (tid < NW) ? sh[par][1][tid] : 0.0f;
            int   ni = (tid < NW) ? shn[par][tid]   : 0;
            z = warp_sum(z);
            y = warp_sum(y);
#pragma unroll
            for (int o = 16; o > 0; o >>= 1)
                ni += __shfl_xor_sync(0xffffffffu, ni, o);
            if (tid == 0) {
                int num_listed = s_nl[par];
                int ignored    = X - ni;
                bool keep      = (num_listed - ignored) > 0;
                if (keep) {
                    acc_loss += -__logf(y / z + 1e-5f);
                    acc_keep += 1.0f;
                }
            }
        }

        if (++s == STAGES) { s = 0; wraps ^= 1; }
        ph = wraps;
    }

    // ---- one global write per CTA, then last-CTA tiny reduce ----
    __syncthreads();
    if (tid == 0) {
        g_part[bid] = make_float2(acc_loss, acc_keep);
        __threadfence();
        unsigned int n = atomicAdd(&g_done, 1u);
        s_last = (n == (unsigned int)(G - 1)) ? 1 : 0;
    }
    __syncthreads();
    if (!s_last) return;
    __threadfence();   // acquire

    float ssum = 0.0f, csum = 0.0f;
    for (int i = tid; i < G; i += BDIM) {
        float2 v = g_part[i];
        ssum += v.x;
        csum += v.y;
    }
    ssum = warp_sum(ssum);
    csum = warp_sum(csum);
    __syncthreads();
    if (l == 0) { sh[0][0][w] = ssum; sh[0][1][w] = csum; }
    __syncthreads();
    if (tid < 32) {
        float x  = (tid < BDIM / 32) ? sh[0][0][tid] : 0.0f;
        float cc = (tid < BDIM / 32) ? sh[0][1][tid] : 0.0f;
        x  = warp_sum(x);
        cc = warp_sum(cc);
        if (tid == 0) {
            out[0] = x / fmaxf(cc, 1.0f);
            g_done = 0;                      // reset for next graph replay
            g_next = 0;
        }
    }
}

// Generic fallback (any nlabels).
__device__ float2 g_row_fb[65536];
__global__ void __launch_bounds__(256)
fused_generic(const float* __restrict__ prd, const int* __restrict__ tgt,
              float* __restrict__ out, int nlabels, int xc, int B)
{
    __shared__ float shf[8];
    __shared__ float shs[8];
    __shared__ float shc[8];
    __shared__ int   s_last;

    const int row = blockIdx.x;
    const int tid = threadIdx.x;
    const int w   = tid >> 5;
    const int l   = tid & 31;

    const float* p    = prd + (size_t)row * nlabels;
    const int*   trow = tgt + (size_t)row * xc;
    const int    X    = xc - 1;

    float lsum = 0.0f;
    for (int i = tid; i < nlabels; i += 256) lsum += __expf(p[i]);

    float sel = 0.0f, nzf = 0.0f;
    for (int j = tid; j < X; j += 256) {
        int lab = trow[j];
        if (lab != 0) { sel += __expf(p[lab]); nzf += 1.0f; }
    }

    float a = warp_sum(lsum), b = warp_sum(sel), c = warp_sum(nzf);
    if (l == 0) { shf[w] = a; shs[w] = b; shc[w] = c; }
    __syncthreads();
    if (tid < 32) {
        float x  = (tid < 8) ? shf[tid] : 0.0f;
        float y  = (tid < 8) ? shs[tid] : 0.0f;
        float cc = (tid < 8) ? shc[tid] : 0.0f;
        x = warp_sum(x); y = warp_sum(y); cc = warp_sum(cc);
        if (tid == 0) {
            int num_listed = trow[X];
            int ignored    = X - (int)(cc + 0.5f);
            bool keep      = (num_listed - ignored) > 0;
            float per      = -__logf(y / x + 1e-5f);
            g_row_fb[row] = make_float2(keep ? per : 0.0f, keep ? 1.0f : 0.0f);
        }
    }
    if (tid == 0) {
        __threadfence();
        unsigned int n = atomicAdd(&g_done, 1u);
        s_last = (n == (unsigned int)(gridDim.x - 1)) ? 1 : 0;
    }
    __syncthreads();
    if (!s_last) return;
    __threadfence();

    float s = 0.0f, c2 = 0.0f;
    for (int i = tid; i < B; i += 256) {
        float2 v = g_row_fb[i];
        s += v.x; c2 += v.y;
    }
    s = warp_sum(s); c2 = warp_sum(c2);
    __syncthreads();
    if (l == 0) { shf[w] = s; shs[w] = c2; }
    __syncthreads();
    if (tid < 32) {
        float x  = (tid < 8) ? shf[tid] : 0.0f;
        float cc = (tid < 8) ? shs[tid] : 0.0f;
        x = warp_sum(x); cc = warp_sum(cc);
        if (tid == 0) { out[0] = x / fmaxf(cc, 1.0f); g_done = 0; }
    }
}

extern "C" void kernel_launch(void* const* d_in, const int* in_sizes, int n_in,
                              void* d_out, int out_size)
{
    const float* prd = (const float*)d_in[0];
    const int*   tgt = (const int*)d_in[1];

    const int xc = 51;                               // X=50 labels + count col
    const int B  = in_sizes[1] / xc;
    const int nlabels = (int)((long long)in_sizes[0] / B);

    if (nlabels == 8192) {
        int sms = 148;
        cudaDeviceGetAttribute(&sms, cudaDevAttrMultiProcessorCount, 0);
        int G = CTAS * sms;                          // CTAS persistent CTAs per SM
        if (G > B)    G = B;
        if (G > MAXG) G = MAXG;
        size_t dyn = (size_t)STAGES * 8192 * sizeof(float);   // 64 KB per CTA
        cudaFuncSetAttribute(pers_kernel<8192>,
                             cudaFuncAttributeMaxDynamicSharedMemorySize, (int)dyn);
        pers_kernel<8192><<<G, BDIM, dyn>>>(prd, tgt, (float*)d_out, xc, B, G);
    } else {
        fused_generic<<<B, 256>>>(prd, tgt, (float*)d_out, nlabels, xc, B);
    }
}

// round 16
// speedup vs baseline: 1.0082x; 1.0082x over previous
#include <cuda_runtime.h>
#include <math.h>

#define BDIM   256
#define STAGES 2          // full-row stages per CTA
#define CTAS   3          // persistent CTAs per SM (3 barrier domains)
#define MAXG   4096

// Scratch (allocation-free): per-CTA partial {loss_sum, keep_count} + queues.
__device__ float2       g_part[MAXG];
__device__ unsigned int g_done = 0;
__device__ unsigned int g_next = 0;    // dynamic row queue head

__device__ __forceinline__ float warp_sum(float v) {
#pragma unroll
    for (int o = 16; o > 0; o >>= 1)
        v += __shfl_xor_sync(0xffffffffu, v, o);
    return v;
}

__device__ __forceinline__ unsigned int smem_u32(const void* p) {
    return (unsigned int)__cvta_generic_to_shared(p);
}
__device__ __forceinline__ void mbar_init(unsigned int mb, unsigned int cnt) {
    asm volatile("mbarrier.init.shared.b64 [%0], %1;" :: "r"(mb), "r"(cnt) : "memory");
}
__device__ __forceinline__ void mbar_expect_tx(unsigned int mb, unsigned int bytes) {
    asm volatile("mbarrier.arrive.expect_tx.shared.b64 _, [%0], %1;"
                 :: "r"(mb), "r"(bytes) : "memory");
}
__device__ __forceinline__ void bulk_g2s(unsigned int dst, const void* src,
                                         unsigned int bytes, unsigned int mb) {
    asm volatile(
        "cp.async.bulk.shared::cta.global.mbarrier::complete_tx::bytes [%0], [%1], %2, [%3];"
        :: "r"(dst), "l"(src), "r"(bytes), "r"(mb) : "memory");
}
__device__ __forceinline__ void mbar_wait(unsigned int mb, unsigned int parity) {
    asm volatile(
        "{\n\t"
        ".reg .pred P;\n\t"
        "WAIT_%=:\n\t"
        "mbarrier.try_wait.parity.acquire.cta.shared::cta.b64 P, [%0], %1, 0x989680;\n\t"
        "@P bra.uni DONE_%=;\n\t"
        "bra.uni WAIT_%=;\n\t"
        "DONE_%=:\n\t"
        "}"
        :: "r"(mb), "r"(parity) : "memory");
}

// FINAL CONFIG (measured 82.0us, HBM 6.40 TB/s ~= achieved ceiling):
// persistent CTA (3/SM = 3 independent barrier domains), 2 x 32KB full-row
// cp.async.bulk stages through smem, dynamic row queue (atomicAdd) for perfect
// load balance across per-SM speed spread. Labels LDG'd at loop top (hidden);
// gather reads the smem-resident row; exp fully hidden under memory; one
// global write per CTA + last-CTA scalar reduce.
template <int NL>
__global__ void __launch_bounds__(BDIM, CTAS)
pers_kernel(const float* __restrict__ prd, const int* __restrict__ tgt,
            float* __restrict__ out, int xc, int B, int G)
{
    constexpr int ROW_BYTES = NL * 4;          // 32768
    constexpr int ROW_F4    = NL / 4;          // 2048 float4

    extern __shared__ float4 stage[];          // STAGES * ROW_F4

    __shared__ __align__(8) unsigned long long mbar_store[STAGES];
    __shared__ int   s_rowid[STAGES];          // row id held in each stage slot
    __shared__ float sh[2][2][BDIM / 32];      // [iter parity][{z,sel}][warp]
    __shared__ int   shn[2][BDIM / 32];        // [iter parity][warp] hit counts
    __shared__ int   s_nl[2];
    __shared__ int   s_last;

    const int tid = threadIdx.x;
    const int w   = tid >> 5;
    const int l   = tid & 31;
    const int X   = xc - 1;
    const int bid = blockIdx.x;

    unsigned int mb[STAGES];
#pragma unroll
    for (int s = 0; s < STAGES; s++) mb[s] = smem_u32(&mbar_store[s]);

    if (tid == 0) {
#pragma unroll
        for (int s = 0; s < STAGES; s++) mbar_init(mb[s], 1);
        // grab the first STAGES rows from the queue and start copies
#pragma unroll
        for (int j = 0; j < STAGES; j++) {
            unsigned int r = atomicAdd(&g_next, 1u);
            s_rowid[j] = (r < (unsigned int)B) ? (int)r : -1;
            if (r < (unsigned int)B) {
                mbar_expect_tx(mb[j], ROW_BYTES);
                bulk_g2s(smem_u32(stage + j * ROW_F4),
                         prd + (size_t)r * NL, ROW_BYTES, mb[j]);
            }
        }
    }
    __syncthreads();

    float acc_loss = 0.0f;   // meaningful in thread 0 only
    float acc_keep = 0.0f;

    int s = 0, ph = 0, wraps = 0;
    for (int k = 0; ; k++) {
        // row id for this slot: written by tid0 >=1 sync ago -> safe
        const int row = s_rowid[s];
        if (row < 0) break;
        const int par = k & 1;

        // labels for THIS row: issue LDG now, consumed mid-compute (hidden)
        int labv = 0;
        if (tid <= X) labv = tgt[(size_t)row * xc + tid];

        mbar_wait(mb[s], ph);

        const float4* rowp = stage + s * ROW_F4;
        const float*  rowf = (const float*)rowp;

        // exp-sum of the whole row from smem
        float lsum = 0.0f;
#pragma unroll
        for (int j = 0; j < 8; j++) {
            float4 v = rowp[tid + j * BDIM];
            lsum += __expf(v.x); lsum += __expf(v.y);
            lsum += __expf(v.z); lsum += __expf(v.w);
        }

        // label gather straight from smem (row is resident)
        bool  hit = (tid < X) && (labv != 0);
        float sel = hit ? __expf(rowf[labv]) : 0.0f;
        if (tid == X) s_nl[par] = labv;        // num_listed

        // per-row block reduction: 2 float warp-sums + ballot popc
        float r0 = warp_sum(lsum);
        float r1 = warp_sum(sel);
        unsigned int bal = __ballot_sync(0xffffffffu, hit);
        if (l == 0) {
            sh[par][0][w] = r0;
            sh[par][1][w] = r1;
            shn[par][w]   = __popc(bal);
        }
        __syncthreads();   // all reads of stage s complete past this point

        // refill stage s with the next queued row
        if (tid == 0) {
            unsigned int nr = atomicAdd(&g_next, 1u);
            s_rowid[s] = (nr < (unsigned int)B) ? (int)nr : -1;
            if (nr < (unsigned int)B) {
                mbar_expect_tx(mb[s], ROW_BYTES);
                bulk_g2s(smem_u32(stage + s * ROW_F4),
                         prd + (size_t)nr * NL, ROW_BYTES, mb[s]);
            }
        }

        if (tid < 32) {
            const int NW = BDIM / 32;
            float z  = (tid < NW) ? sh[par][0][tid] : 0.0f;
            float y  = (tid < NW) ? sh[par][1][tid] : 0.0f;
            int   ni = (tid < NW) ? shn[par][tid]   : 0;
            z = warp_sum(z);
            y = warp_sum(y);
#pragma unroll
            for (int o = 16; o > 0; o >>= 1)
                ni += __shfl_xor_sync(0xffffffffu, ni, o);
            if (tid == 0) {
                int num_listed = s_nl[par];
                int ignored    = X - ni;
                bool keep      = (num_listed - ignored) > 0;
                if (keep) {
                    acc_loss += -__logf(y / z + 1e-5f);
                    acc_keep += 1.0f;
                }
            }
        }

        if (++s == STAGES) { s = 0; wraps ^= 1; }
        ph = wraps;
    }

    // ---- one global write per CTA, then last-CTA tiny reduce ----
    __syncthreads();
    if (tid == 0) {
        g_part[bid] = make_float2(acc_loss, acc_keep);
        __threadfence();
        unsigned int n = atomicAdd(&g_done, 1u);
        s_last = (n == (unsigned int)(G - 1)) ? 1 : 0;
    }
    __syncthreads();
    if (!s_last) return;
    __threadfence();   // acquire

    float ssum = 0.0f, csum = 0.0f;
    for (int i = tid; i < G; i += BDIM) {
        float2 v = g_part[i];
        ssum += v.x;
        csum += v.y;
    }
    ssum = warp_sum(ssum);
    csum = warp_sum(csum);
    __syncthreads();
    if (l == 0) { sh[0][0][w] = ssum; sh[0][1][w] = csum; }
    __syncthreads();
    if (tid < 32) {
        float x  = (tid < BDIM / 32) ? sh[0][0][tid] : 0.0f;
        float cc = (tid < BDIM / 32) ? sh[0][1][tid] : 0.0f;
        x  = warp_sum(x);
        cc = warp_sum(cc);
        if (tid == 0) {
            out[0] = x / fmaxf(cc, 1.0f);
            g_done = 0;                      // reset for next graph replay
            g_next = 0;
        }
    }
}

// Generic fallback (any nlabels).
__device__ float2 g_row_fb[65536];
__global__ void __launch_bounds__(256)
fused_generic(const float* __restrict__ prd, const int* __restrict__ tgt,
              float* __restrict__ out, int nlabels, int xc, int B)
{
    __shared__ float shf[8];
    __shared__ float shs[8];
    __shared__ float shc[8];
    __shared__ int   s_last;

    const int row = blockIdx.x;
    const int tid = threadIdx.x;
    const int w   = tid >> 5;
    const int l   = tid & 31;

    const float* p    = prd + (size_t)row * nlabels;
    const int*   trow = tgt + (size_t)row * xc;
    const int    X    = xc - 1;

    float lsum = 0.0f;
    for (int i = tid; i < nlabels; i += 256) lsum += __expf(p[i]);

    float sel = 0.0f, nzf = 0.0f;
    for (int j = tid; j < X; j += 256) {
        int lab = trow[j];
        if (lab != 0) { sel += __expf(p[lab]); nzf += 1.0f; }
    }

    float a = warp_sum(lsum), b = warp_sum(sel), c = warp_sum(nzf);
    if (l == 0) { shf[w] = a; shs[w] = b; shc[w] = c; }
    __syncthreads();
    if (tid < 32) {
        float x  = (tid < 8) ? shf[tid] : 0.0f;
        float y  = (tid < 8) ? shs[tid] : 0.0f;
        float cc = (tid < 8) ? shc[tid] : 0.0f;
        x = warp_sum(x); y = warp_sum(y); cc = warp_sum(cc);
        if (tid == 0) {
            int num_listed = trow[X];
            int ignored    = X - (int)(cc + 0.5f);
            bool keep      = (num_listed - ignored) > 0;
            float per      = -__logf(y / x + 1e-5f);
            g_row_fb[row] = make_float2(keep ? per : 0.0f, keep ? 1.0f : 0.0f);
        }
    }
    if (tid == 0) {
        __threadfence();
        unsigned int n = atomicAdd(&g_done, 1u);
        s_last = (n == (unsigned int)(gridDim.x - 1)) ? 1 : 0;
    }
    __syncthreads();
    if (!s_last) return;
    __threadfence();

    float s = 0.0f, c2 = 0.0f;
    for (int i = tid; i < B; i += 256) {
        float2 v = g_row_fb[i];
        s += v.x; c2 += v.y;
    }
    s = warp_sum(s); c2 = warp_sum(c2);
    __syncthreads();
    if (l == 0) { shf[w] = s; shs[w] = c2; }
    __syncthreads();
    if (tid < 32) {
        float x  = (tid < 8) ? shf[tid] : 0.0f;
        float cc = (tid < 8) ? shs[tid] : 0.0f;
        x = warp_sum(x); cc = warp_sum(cc);
        if (tid == 0) { out[0] = x / fmaxf(cc, 1.0f); g_done = 0; }
    }
}

extern "C" void kernel_launch(void* const* d_in, const int* in_sizes, int n_in,
                              void* d_out, int out_size)
{
    const float* prd = (const float*)d_in[0];
    const int*   tgt = (const int*)d_in[1];

    const int xc = 51;                               // X=50 labels + count col
    const int B  = in_sizes[1] / xc;
    const int nlabels = (int)((long long)in_sizes[0] / B);

    if (nlabels == 8192) {
        int sms = 148;
        cudaDeviceGetAttribute(&sms, cudaDevAttrMultiProcessorCount, 0);
        int G = CTAS * sms;                          // CTAS persistent CTAs per SM
        if (G > B)    G = B;
        if (G > MAXG) G = MAXG;
        size_t dyn = (size_t)STAGES * 8192 * sizeof(float);   // 64 KB per CTA
        cudaFuncSetAttribute(pers_kernel<8192>,
                             cudaFuncAttributeMaxDynamicSharedMemorySize, (int)dyn);
        pers_kernel<8192><<<G, BDIM, dyn>>>(prd, tgt, (float*)d_out, xc, B, G);
    } else {
        fused_generic<<<B, 256>>>(prd, tgt, (float*)d_out, nlabels, xc, B);
    }
}

// round 17
// speedup vs baseline: 1.0086x; 1.0004x over previous
#include <cuda_runtime.h>
#include <math.h>

#define BDIM   256
#define STAGES 2          // full-row stages per CTA
#define CTAS   3          // persistent CTAs per SM (3 barrier domains)
#define MAXG   4096

// Scratch (allocation-free): per-CTA partial {loss_sum, keep_count} + queues.
__device__ float2       g_part[MAXG];
__device__ unsigned int g_done = 0;
__device__ unsigned int g_next = 0;    // dynamic row queue head

__device__ __forceinline__ float warp_sum(float v) {
#pragma unroll
    for (int o = 16; o > 0; o >>= 1)
        v += __shfl_xor_sync(0xffffffffu, v, o);
    return v;
}

__device__ __forceinline__ unsigned int smem_u32(const void* p) {
    return (unsigned int)__cvta_generic_to_shared(p);
}
__device__ __forceinline__ void mbar_init(unsigned int mb, unsigned int cnt) {
    asm volatile("mbarrier.init.shared.b64 [%0], %1;" :: "r"(mb), "r"(cnt) : "memory");
}
__device__ __forceinline__ void mbar_expect_tx(unsigned int mb, unsigned int bytes) {
    asm volatile("mbarrier.arrive.expect_tx.shared.b64 _, [%0], %1;"
                 :: "r"(mb), "r"(bytes) : "memory");
}
__device__ __forceinline__ void bulk_g2s(unsigned int dst, const void* src,
                                         unsigned int bytes, unsigned int mb) {
    asm volatile(
        "cp.async.bulk.shared::cta.global.mbarrier::complete_tx::bytes [%0], [%1], %2, [%3];"
        :: "r"(dst), "l"(src), "r"(bytes), "r"(mb) : "memory");
}
__device__ __forceinline__ void mbar_wait(unsigned int mb, unsigned int parity) {
    asm volatile(
        "{\n\t"
        ".reg .pred P;\n\t"
        "WAIT_%=:\n\t"
        "mbarrier.try_wait.parity.acquire.cta.shared::cta.b64 P, [%0], %1, 0x989680;\n\t"
        "@P bra.uni DONE_%=;\n\t"
        "bra.uni WAIT_%=;\n\t"
        "DONE_%=:\n\t"
        "}"
        :: "r"(mb), "r"(parity) : "memory");
}

// FINAL CONFIG (R14/R16 = 82.0us, HBM 6.41 TB/s) + ticket prefetch:
// thread 0 holds the next queue ticket in a register, so the refill bulk_g2s
// issues immediately after the stage-release sync instead of waiting ~318cyc
// on the ATOMG result. The following ticket's atomicAdd overlaps the next
// ~3200-cycle row period.
template <int NL>
__global__ void __launch_bounds__(BDIM, CTAS)
pers_kernel(const float* __restrict__ prd, const int* __restrict__ tgt,
            float* __restrict__ out, int xc, int B, int G)
{
    constexpr int ROW_BYTES = NL * 4;          // 32768
    constexpr int ROW_F4    = NL / 4;          // 2048 float4

    extern __shared__ float4 stage[];          // STAGES * ROW_F4

    __shared__ __align__(8) unsigned long long mbar_store[STAGES];
    __shared__ int   s_rowid[STAGES];          // row id held in each stage slot
    __shared__ float sh[2][2][BDIM / 32];      // [iter parity][{z,sel}][warp]
    __shared__ int   shn[2][BDIM / 32];        // [iter parity][warp] hit counts
    __shared__ int   s_nl[2];
    __shared__ int   s_last;

    const int tid = threadIdx.x;
    const int w   = tid >> 5;
    const int l   = tid & 31;
    const int X   = xc - 1;
    const int bid = blockIdx.x;

    unsigned int mb[STAGES];
#pragma unroll
    for (int s = 0; s < STAGES; s++) mb[s] = smem_u32(&mbar_store[s]);

    unsigned int next_row = 0xffffffffu;       // thread 0: prefetched ticket

    if (tid == 0) {
#pragma unroll
        for (int s = 0; s < STAGES; s++) mbar_init(mb[s], 1);
        // grab the first STAGES rows and start copies
#pragma unroll
        for (int j = 0; j < STAGES; j++) {
            unsigned int r = atomicAdd(&g_next, 1u);
            s_rowid[j] = (r < (unsigned int)B) ? (int)r : -1;
            if (r < (unsigned int)B) {
                mbar_expect_tx(mb[j], ROW_BYTES);
                bulk_g2s(smem_u32(stage + j * ROW_F4),
                         prd + (size_t)r * NL, ROW_BYTES, mb[j]);
            }
        }
        // prefetch the first refill ticket
        next_row = atomicAdd(&g_next, 1u);
    }
    __syncthreads();

    float acc_loss = 0.0f;   // meaningful in thread 0 only
    float acc_keep = 0.0f;

    int s = 0, ph = 0, wraps = 0;
    for (int k = 0; ; k++) {
        // row id for this slot: written by tid0 >=1 sync ago -> safe
        const int row = s_rowid[s];
        if (row < 0) break;
        const int par = k & 1;

        // labels for THIS row: issue LDG now, consumed mid-compute (hidden)
        int labv = 0;
        if (tid <= X) labv = tgt[(size_t)row * xc + tid];

        mbar_wait(mb[s], ph);

        const float4* rowp = stage + s * ROW_F4;
        const float*  rowf = (const float*)rowp;

        // exp-sum of the whole row from smem
        float lsum = 0.0f;
#pragma unroll
        for (int j = 0; j < 8; j++) {
            float4 v = rowp[tid + j * BDIM];
            lsum += __expf(v.x); lsum += __expf(v.y);
            lsum += __expf(v.z); lsum += __expf(v.w);
        }

        // label gather straight from smem (row is resident)
        bool  hit = (tid < X) && (labv != 0);
        float sel = hit ? __expf(rowf[labv]) : 0.0f;
        if (tid == X) s_nl[par] = labv;        // num_listed

        // per-row block reduction: 2 float warp-sums + ballot popc
        float r0 = warp_sum(lsum);
        float r1 = warp_sum(sel);
        unsigned int bal = __ballot_sync(0xffffffffu, hit);
        if (l == 0) {
            sh[par][0][w] = r0;
            sh[par][1][w] = r1;
            shn[par][w]   = __popc(bal);
        }
        __syncthreads();   // all reads of stage s complete past this point

        // refill stage s with the PREFETCHED ticket (no ATOMG on this path),
        // then immediately prefetch the following ticket (latency overlapped)
        if (tid == 0) {
            unsigned int nr = next_row;
            s_rowid[s] = (nr < (unsigned int)B) ? (int)nr : -1;
            if (nr < (unsigned int)B) {
                mbar_expect_tx(mb[s], ROW_BYTES);
                bulk_g2s(smem_u32(stage + s * ROW_F4),
                         prd + (size_t)nr * NL, ROW_BYTES, mb[s]);
                next_row = atomicAdd(&g_next, 1u);
            }
        }

        if (tid < 32) {
            const int NW = BDIM / 32;
            float z  = (tid < NW) ? sh[par][0][tid] : 0.0f;
            float y  = (tid < NW) ? sh[par][1][tid] : 0.0f;
            int   ni = (tid < NW) ? shn[par][tid]   : 0;
            z = warp_sum(z);
            y = warp_sum(y);
#pragma unroll
            for (int o = 16; o > 0; o >>= 1)
                ni += __shfl_xor_sync(0xffffffffu, ni, o);
            if (tid == 0) {
                int num_listed = s_nl[par];
                int ignored    = X - ni;
                bool keep      = (num_listed - ignored) > 0;
                if (keep) {
                    acc_loss += -__logf(y / z + 1e-5f);
                    acc_keep += 1.0f;
                }
            }
        }

        if (++s == STAGES) { s = 0; wraps ^= 1; }
        ph = wraps;
    }

    // ---- one global write per CTA, then last-CTA tiny reduce ----
    __syncthreads();
    if (tid == 0) {
        g_part[bid] = make_float2(acc_loss, acc_keep);
        __threadfence();
        unsigned int n = atomicAdd(&g_done, 1u);
        s_last = (n == (unsigned int)(G - 1)) ? 1 : 0;
    }
    __syncthreads();
    if (!s_last) return;
    __threadfence();   // acquire

    float ssum = 0.0f, csum = 0.0f;
    for (int i = tid; i < G; i += BDIM) {
        float2 v = g_part[i];
        ssum += v.x;
        csum += v.y;
    }
    ssum = warp_sum(ssum);
    csum = warp_sum(csum);
    __syncthreads();
    if (l == 0) { sh[0][0][w] = ssum; sh[0][1][w] = csum; }
    __syncthreads();
    if (tid < 32) {
        float x  = (tid < BDIM / 32) ? sh[0][0][tid] : 0.0f;
        float cc = (tid < BDIM / 32) ? sh[0][1][tid] : 0.0f;
        x  = warp_sum(x);
        cc = warp_sum(cc);
        if (tid == 0) {
            out[0] = x / fmaxf(cc, 1.0f);
            g_done = 0;                      // reset for next graph replay
            g_next = 0;
        }
    }
}

// Generic fallback (any nlabels).
__device__ float2 g_row_fb[65536];
__global__ void __launch_bounds__(256)
fused_generic(const float* __restrict__ prd, const int* __restrict__ tgt,
              float* __restrict__ out, int nlabels, int xc, int B)
{
    __shared__ float shf[8];
    __shared__ float shs[8];
    __shared__ float shc[8];
    __shared__ int   s_last;

    const int row = blockIdx.x;
    const int tid = threadIdx.x;
    const int w   = tid >> 5;
    const int l   = tid & 31;

    const float* p    = prd + (size_t)row * nlabels;
    const int*   trow = tgt + (size_t)row * xc;
    const int    X    = xc - 1;

    float lsum = 0.0f;
    for (int i = tid; i < nlabels; i += 256) lsum += __expf(p[i]);

    float sel = 0.0f, nzf = 0.0f;
    for (int j = tid; j < X; j += 256) {
        int lab = trow[j];
        if (lab != 0) { sel += __expf(p[lab]); nzf += 1.0f; }
    }

    float a = warp_sum(lsum), b = warp_sum(sel), c = warp_sum(nzf);
    if (l == 0) { shf[w] = a; shs[w] = b; shc[w] = c; }
    __syncthreads();
    if (tid < 32) {
        float x  = (tid < 8) ? shf[tid] : 0.0f;
        float y  = (tid < 8) ? shs[tid] : 0.0f;
        float cc = (tid < 8) ? shc[tid] : 0.0f;
        x = warp_sum(x); y = warp_sum(y); cc = warp_sum(cc);
        if (tid == 0) {
            int num_listed = trow[X];
            int ignored    = X - (int)(cc + 0.5f);
            bool keep      = (num_listed - ignored) > 0;
            float per      = -__logf(y / x + 1e-5f);
            g_row_fb[row] = make_float2(keep ? per : 0.0f, keep ? 1.0f : 0.0f);
        }
    }
    if (tid == 0) {
        __threadfence();
        unsigned int n = atomicAdd(&g_done, 1u);
        s_last = (n == (unsigned int)(gridDim.x - 1)) ? 1 : 0;
    }
    __syncthreads();
    if (!s_last) return;
    __threadfence();

    float s = 0.0f, c2 = 0.0f;
    for (int i = tid; i < B; i += 256) {
        float2 v = g_row_fb[i];
        s += v.x; c2 += v.y;
    }
    s = warp_sum(s); c2 = warp_sum(c2);
    __syncthreads();
    if (l == 0) { shf[w] = s; shs[w] = c2; }
    __syncthreads();
    if (tid < 32) {
        float x  = (tid < 8) ? shf[tid] : 0.0f;
        float cc = (tid < 8) ? shs[tid] : 0.0f;
        x = warp_sum(x); cc = warp_sum(cc);
        if (tid == 0) { out[0] = x / fmaxf(cc, 1.0f); g_done = 0; }
    }
}

extern "C" void kernel_launch(void* const* d_in, const int* in_sizes, int n_in,
                              void* d_out, int out_size)
{
    const float* prd = (const float*)d_in[0];
    const int*   tgt = (const int*)d_in[1];

    const int xc = 51;                               // X=50 labels + count col
    const int B  = in_sizes[1] / xc;
    const int nlabels = (int)((long long)in_sizes[0] / B);

    if (nlabels == 8192) {
        int sms = 148;
        cudaDeviceGetAttribute(&sms, cudaDevAttrMultiProcessorCount, 0);
        int G = CTAS * sms;                          // CTAS persistent CTAs per SM
        if (G > B)    G = B;
        if (G > MAXG) G = MAXG;
        size_t dyn = (size_t)STAGES * 8192 * sizeof(float);   // 64 KB per CTA
        cudaFuncSetAttribute(pers_kernel<8192>,
                             cudaFuncAttributeMaxDynamicSharedMemorySize, (int)dyn);
        pers_kernel<8192><<<G, BDIM, dyn>>>(prd, tgt, (float*)d_out, xc, B, G);
    } else {
        fused_generic<<<B, 256>>>(prd, tgt, (float*)d_out, nlabels, xc, B);
    }
}